// round 3
// baseline (speedup 1.0000x reference)
#include <cuda_runtime.h>

#define E_NUM 8192
#define D 64

// ---------------- scratch (no allocs allowed) ----------------
__device__ float g_cp[D], g_cm[D];         // relu(v+), relu(v-)
__device__ int   g_flag;                   // 1 => biases nonzero -> generic path
__device__ float g_P[E_NUM], g_M[E_NUM];   // segment sums of max(x,0), max(-x,0)
__device__ float g_pooled[E_NUM * D];      // generic-path pooled
__device__ float g_gsum[D];                // sum over events of g

// ---------------- K0: zero scratch, build c+/c-, bias check ----------------
__global__ void k_prep(const float* __restrict__ w0, const float* __restrict__ b0,
                       const float* __restrict__ W1, const float* __restrict__ b1)
{
    const int tid = threadIdx.x;
    const int gid = blockIdx.x * blockDim.x + tid;
    const int gs  = gridDim.x * blockDim.x;

    for (int i = gid; i < E_NUM * D; i += gs) g_pooled[i] = 0.f;
    for (int i = gid; i < E_NUM; i += gs) { g_P[i] = 0.f; g_M[i] = 0.f; }
    if (gid < D) g_gsum[gid] = 0.f;

    if (blockIdx.x == 0) {
        int nz = 0;
        if (tid < D) nz = (b0[tid] != 0.f) || (b1[tid] != 0.f);
        int any = __syncthreads_or(nz);
        if (tid == 0) g_flag = any ? 1 : 0;
        if (tid < D) {
            float vp = 0.f, vn = 0.f;
            #pragma unroll
            for (int j = 0; j < D; j++) {
                float w   = w0[j];
                float col = W1[j * D + tid];
                vp += fmaxf(w, 0.f)  * col;
                vn += fmaxf(-w, 0.f) * col;
            }
            g_cp[tid] = fmaxf(vp, 0.f);
            g_cm[tid] = fmaxf(vn, 0.f);
        }
    }
}

// ---------------- K1: stage-1 phi + segment pooling ----------------
__global__ void __launch_bounds__(256) k_stage1(
    const float* __restrict__ x, const int* __restrict__ seg, int n,
    const float* __restrict__ w0, const float* __restrict__ b0,
    const float* __restrict__ W1, const float* __restrict__ b1)
{
    const int flag = g_flag;   // uniform across grid

    if (!flag) {
        // ---- fast path: two scalar segment sums, fully HBM-bound ----
        const int lane   = threadIdx.x & 31;
        const int warp   = (blockIdx.x * blockDim.x + threadIdx.x) >> 5;
        const int nwarps = (gridDim.x * blockDim.x) >> 5;
        const int G      = n >> 2;                       // float4 groups
        const int gpw    = (G + nwarps - 1) / nwarps;    // groups per warp

        const long long gbase = (long long)warp * gpw;
        const long long gend0 = gbase + gpw;
        const long long gend  = gend0 < (long long)G ? gend0 : (long long)G;

        const float4* x4 = (const float4*)x;
        const int4*   s4 = (const int4*)seg;

        int   cur = -1;
        float aP = 0.f, aM = 0.f;

        for (long long g = gbase + lane; g < gend; g += 32) {
            float4 xv = x4[g];
            int4   sv = s4[g];
            int   ss[4] = {sv.x, sv.y, sv.z, sv.w};
            float xs[4] = {xv.x, xv.y, xv.z, xv.w};
            #pragma unroll
            for (int u = 0; u < 4; u++) {
                int s = ss[u];
                if (s != cur) {
                    if (cur >= 0) { atomicAdd(&g_P[cur], aP); atomicAdd(&g_M[cur], aM); }
                    cur = s; aP = 0.f; aM = 0.f;
                }
                aP += fmaxf(xs[u],  0.f);
                aM += fmaxf(-xs[u], 0.f);
            }
        }
        if (cur >= 0) { atomicAdd(&g_P[cur], aP); atomicAdd(&g_M[cur], aM); }

        // scalar tail (n % 4)
        if (warp == 0 && lane == 0) {
            for (int i = G * 4; i < n; i++) {
                float xv = x[i]; int s = seg[i];
                atomicAdd(&g_P[s], fmaxf(xv,  0.f));
                atomicAdd(&g_M[s], fmaxf(-xv, 0.f));
            }
        }
    } else {
        // ---- generic fallback (never taken for this problem's inputs) ----
        __shared__ float sw0[D], sb0[D], sW1[D * D], sb1[D];
        for (int i = threadIdx.x; i < D; i += blockDim.x) {
            sw0[i] = w0[i]; sb0[i] = b0[i]; sb1[i] = b1[i];
        }
        for (int i = threadIdx.x; i < D * D; i += blockDim.x) sW1[i] = W1[i];
        __syncthreads();

        const int stride = gridDim.x * blockDim.x;
        for (int i = blockIdx.x * blockDim.x + threadIdx.x; i < n; i += stride) {
            float xv = x[i];
            int   e  = seg[i];
            float h1[D];
            #pragma unroll
            for (int j = 0; j < D; j++) h1[j] = fmaxf(xv * sw0[j] + sb0[j], 0.f);
            #pragma unroll 2
            for (int k = 0; k < D; k++) {
                float acc = sb1[k];
                #pragma unroll
                for (int j = 0; j < D; j++) acc += h1[j] * sW1[j * D + k];
                atomicAdd(&g_pooled[e * D + k], fmaxf(acc, 0.f));
            }
        }
    }
}

// ---------------- K2: fused 5-layer per-event MLP + global sum ----------------
__global__ void __launch_bounds__(256) k_events(
    const float* __restrict__ r1w0, const float* __restrict__ r1b0,
    const float* __restrict__ r1w1, const float* __restrict__ r1b1,
    const float* __restrict__ o1w,  const float* __restrict__ o1b,
    const float* __restrict__ p2w0, const float* __restrict__ p2b0,
    const float* __restrict__ p2w1, const float* __restrict__ p2b1)
{
    __shared__ float shW[D * D];        // current layer weights
    __shared__ float shB[D];
    __shared__ float tile[64 * 65];     // 64 events x 64 feats, padded
    __shared__ float shc[2 * D];        // cp, cm
    __shared__ float red[4 * D];

    const int tid  = threadIdx.x;
    const int e0   = blockIdx.x * 64;
    const int flag = g_flag;

    if (tid < D) { shc[tid] = g_cp[tid]; shc[D + tid] = g_cm[tid]; }
    __syncthreads();

    // build input tile (pooled rows)
    #pragma unroll
    for (int s = 0; s < 16; s++) {
        int idx = tid + s * 256;
        int t = idx >> 6, j = idx & 63;
        float v;
        if (flag) v = g_pooled[(e0 + t) * D + j];
        else      v = g_P[e0 + t] * shc[j] + g_M[e0 + t] * shc[D + j];
        tile[t * 65 + j] = v;
    }
    __syncthreads();

    const float* Ws[5] = {r1w0, r1w1, o1w, p2w0, p2w1};
    const float* Bs[5] = {r1b0, r1b1, o1b, p2b0, p2b1};

    const int tr = tid >> 4;    // 0..15 -> 4-event group
    const int tc = tid & 15;    // 0..15 -> 4-feat group
    const int eb = tr * 4;
    const int kb = tc * 4;

    for (int L = 0; L < 5; L++) {
        const float4* Wg = (const float4*)Ws[L];
        #pragma unroll
        for (int s = 0; s < 4; s++)
            ((float4*)shW)[tid + s * 256] = Wg[tid + s * 256];
        if (tid < D) shB[tid] = Bs[L][tid];
        __syncthreads();

        float acc[4][4];
        #pragma unroll
        for (int a = 0; a < 4; a++)
            #pragma unroll
            for (int b = 0; b < 4; b++) acc[a][b] = shB[kb + b];

        #pragma unroll 8
        for (int j = 0; j < D; j++) {
            float4 wv = *(const float4*)&shW[j * D + kb];
            float a0 = tile[(eb + 0) * 65 + j];
            float a1 = tile[(eb + 1) * 65 + j];
            float a2 = tile[(eb + 2) * 65 + j];
            float a3 = tile[(eb + 3) * 65 + j];
            acc[0][0] += a0 * wv.x; acc[0][1] += a0 * wv.y; acc[0][2] += a0 * wv.z; acc[0][3] += a0 * wv.w;
            acc[1][0] += a1 * wv.x; acc[1][1] += a1 * wv.y; acc[1][2] += a1 * wv.z; acc[1][3] += a1 * wv.w;
            acc[2][0] += a2 * wv.x; acc[2][1] += a2 * wv.y; acc[2][2] += a2 * wv.z; acc[2][3] += a2 * wv.w;
            acc[3][0] += a3 * wv.x; acc[3][1] += a3 * wv.y; acc[3][2] += a3 * wv.z; acc[3][3] += a3 * wv.w;
        }
        __syncthreads();
        #pragma unroll
        for (int a = 0; a < 4; a++)
            #pragma unroll
            for (int b = 0; b < 4; b++)
                tile[(eb + a) * 65 + kb + b] = fmaxf(acc[a][b], 0.f);
        __syncthreads();
    }

    // reduce tile over its 64 events -> 64 partials, atomic into g_gsum
    {
        const int k    = tid & 63;
        const int part = tid >> 6;   // 0..3
        float s = 0.f;
        #pragma unroll
        for (int t = part * 16; t < part * 16 + 16; t++) s += tile[t * 65 + k];
        red[part * D + k] = s;
        __syncthreads();
        if (tid < D) {
            float tot = red[tid] + red[D + tid] + red[2 * D + tid] + red[3 * D + tid];
            atomicAdd(&g_gsum[tid], tot);
        }
    }
}

// ---------------- K3: final rho2 + output ----------------
__global__ void k_final(const float* __restrict__ r2w0, const float* __restrict__ r2b0,
                        const float* __restrict__ r2w1, const float* __restrict__ r2b1,
                        const float* __restrict__ o2w,  const float* __restrict__ o2b,
                        float* __restrict__ out)
{
    __shared__ float s0[D], s1[D], s2[D];
    const int tid = threadIdx.x;
    if (tid < D) s0[tid] = g_gsum[tid];
    __syncthreads();
    if (tid < D) {
        float a = r2b0[tid];
        #pragma unroll
        for (int j = 0; j < D; j++) a += s0[j] * r2w0[j * D + tid];
        s1[tid] = fmaxf(a, 0.f);
    }
    __syncthreads();
    if (tid < D) {
        float a = r2b1[tid];
        #pragma unroll
        for (int j = 0; j < D; j++) a += s1[j] * r2w1[j * D + tid];
        s2[tid] = fmaxf(a, 0.f);
    }
    __syncthreads();
    if (tid < 10) {
        float a = o2b[tid];
        #pragma unroll
        for (int j = 0; j < D; j++) a += s2[j] * o2w[j * 10 + tid];
        out[tid] = a;
    }
}

// ---------------- launch ----------------
extern "C" void kernel_launch(void* const* d_in, const int* in_sizes, int n_in,
                              void* d_out, int out_size)
{
    const float* x    = (const float*)d_in[0];
    const int*   seg  = (const int*)  d_in[1];
    const float* p1w0 = (const float*)d_in[2];
    const float* p1b0 = (const float*)d_in[3];
    const float* p1w1 = (const float*)d_in[4];
    const float* p1b1 = (const float*)d_in[5];
    const float* r1w0 = (const float*)d_in[6];
    const float* r1b0 = (const float*)d_in[7];
    const float* r1w1 = (const float*)d_in[8];
    const float* r1b1 = (const float*)d_in[9];
    const float* o1w  = (const float*)d_in[10];
    const float* o1b  = (const float*)d_in[11];
    const float* p2w0 = (const float*)d_in[12];
    const float* p2b0 = (const float*)d_in[13];
    const float* p2w1 = (const float*)d_in[14];
    const float* p2b1 = (const float*)d_in[15];
    const float* r2w0 = (const float*)d_in[16];
    const float* r2b0 = (const float*)d_in[17];
    const float* r2w1 = (const float*)d_in[18];
    const float* r2b1 = (const float*)d_in[19];
    const float* o2w  = (const float*)d_in[20];
    const float* o2b  = (const float*)d_in[21];
    const int n = in_sizes[0];

    k_prep  <<<128, 256>>>(p1w0, p1b0, p1w1, p1b1);
    k_stage1<<<256, 256>>>(x, seg, n, p1w0, p1b0, p1w1, p1b1);
    k_events<<<E_NUM / 64, 256>>>(r1w0, r1b0, r1w1, r1b1, o1w, o1b,
                                  p2w0, p2b0, p2w1, p2b1);
    k_final <<<1, 128>>>(r2w0, r2b0, r2w1, r2b1, o2w, o2b, (float*)d_out);
}